// round 2
// baseline (speedup 1.0000x reference)
#include <cuda_runtime.h>
#include <cstdint>

// Problem constants: T=1024, B=64, I=128, H=512, L=2
#define TT   1024
#define BB   64
#define II   128
#define HH   512
#define NCTA 128
#define NTHR 128

// Shared memory layout (floats) for the persistent LSTM kernel
#define WS_STRIDE   514                 // weight row stride (bank-conflict-free)
#define ACT_STRIDE  66                  // activation chunk row stride
#define ACT_BUF     (64 * ACT_STRIDE)   // 4224 floats per buffer
#define OFF_W       0
#define OFF_ACT     (64 * WS_STRIDE)                 // 32896
#define OFF_GATES   (OFF_ACT + 2 * ACT_BUF)          // 41344
#define OFF_BIAS    (OFF_GATES + 64 * 20)            // 42624
#define SMEM_FLOATS (OFF_BIAS + 32)                  // 42656
#define SMEM_BYTES  (SMEM_FLOATS * 4)                // 170624

// ---------------------------------------------------------------------------
// Device scratch (no cudaMalloc allowed)
// ---------------------------------------------------------------------------
__device__ float g_inp[(size_t)TT * BB * HH];    // sigmoid(x @ w_in^T + b_in)
__device__ float g_h1all[(size_t)TT * BB * HH];  // layer-1 h per step
__device__ float g_hbuf[2][2][BB * HH];          // [layer][parity][b*H]
__device__ unsigned int g_count = 0;
__device__ unsigned int g_epoch = 0;

// ---------------------------------------------------------------------------
// Helpers
// ---------------------------------------------------------------------------
__device__ __forceinline__ float2 ffma2(float2 a, float2 b, float2 c) {
    unsigned long long ua = *reinterpret_cast<unsigned long long*>(&a);
    unsigned long long ub = *reinterpret_cast<unsigned long long*>(&b);
    unsigned long long uc = *reinterpret_cast<unsigned long long*>(&c);
    unsigned long long ud;
    asm("fma.rn.f32x2 %0, %1, %2, %3;" : "=l"(ud) : "l"(ua), "l"(ub), "l"(uc));
    return *reinterpret_cast<float2*>(&ud);
}

__device__ __forceinline__ float sigm(float x) {
    return 1.0f / (1.0f + __expf(-x));
}
// tanh via exp: accurate to ~1e-6, handles +/-inf saturation correctly in fp32
__device__ __forceinline__ float tanh_a(float x) {
    return 1.0f - 2.0f / (__expf(2.0f * x) + 1.0f);
}

// Grid-wide barrier. All NCTA CTAs are co-resident (1 CTA/SM via 171KB smem),
// so spinning is deadlock-free. Epoch increases monotonically; count returns
// to 0 after every barrier, so state is clean across graph replays.
__device__ __forceinline__ void gbar() {
    __threadfence();
    __syncthreads();
    if (threadIdx.x == 0) {
        unsigned e = *(volatile unsigned*)&g_epoch;
        unsigned a = atomicAdd(&g_count, 1u);
        if (a == NCTA - 1) {
            *(volatile unsigned*)&g_count = 0u;
            __threadfence();
            *(volatile unsigned*)&g_epoch = e + 1u;
        } else {
            while (*(volatile unsigned*)&g_epoch == e) { __nanosleep(32); }
        }
        __threadfence();
    }
    __syncthreads();
}

// Load one 64x64 activation chunk (gmem, L2-coherent) into registers.
// w = warp id (tid>>5), c2 = lane (tid&31). Row = 4*i + w, 32 float2/row.
__device__ __forceinline__ void ldg_chunk(const float* __restrict__ src, int k0,
                                          int w, int c2, float2* r) {
#pragma unroll
    for (int i = 0; i < 16; i++) {
        const float* p = src + (size_t)(4 * i + w) * HH + k0;
        r[i] = __ldcg(reinterpret_cast<const float2*>(p) + c2);
    }
}

__device__ __forceinline__ void sts_chunk(float* buf, int w, int c2, const float2* r) {
#pragma unroll
    for (int i = 0; i < 16; i++) {
        *reinterpret_cast<float2*>(buf + (4 * i + w) * ACT_STRIDE + 2 * c2) = r[i];
    }
}

// Accumulate 64 k-values of the gate dot-products.
// Thread owns 4 batches (bq*4..+3) x 2 gate rows. 6 LDS.64 + 8 FFMA2 per k2.
__device__ __forceinline__ void compute_chunk(const float* __restrict__ buf,
                                              const float* __restrict__ wk0,
                                              const float* __restrict__ wk1,
                                              int bq, float2 acc[4][2]) {
    const float* ab = buf + bq * 4 * ACT_STRIDE;
#pragma unroll
    for (int kk = 0; kk < 32; kk++) {
        float2 w0 = *reinterpret_cast<const float2*>(wk0 + 2 * kk);
        float2 w1 = *reinterpret_cast<const float2*>(wk1 + 2 * kk);
#pragma unroll
        for (int i = 0; i < 4; i++) {
            float2 a = *reinterpret_cast<const float2*>(ab + i * ACT_STRIDE + 2 * kk);
            acc[i][0] = ffma2(a, w0, acc[i][0]);
            acc[i][1] = ffma2(a, w1, acc[i][1]);
        }
    }
}

// ---------------------------------------------------------------------------
// Persistent recurrent kernel. 128 CTAs x 128 threads, 1 CTA/SM.
// CTA owns hidden units [cta*4, cta*4+4) of both layers.
// Local gate row lr = ul*4 + gt  (gt in PyTorch order i,f,g,o),
// global row gr = gt*H + cta*4 + ul.
// ---------------------------------------------------------------------------
__global__ void __launch_bounds__(NTHR, 1) lstm_kernel(
    const float* __restrict__ w_ih, const float* __restrict__ w_hh,
    const float* __restrict__ b_ih, const float* __restrict__ b_hh)
{
    extern __shared__ float sm[];
    float* w_s     = sm + OFF_W;      // [64 rows][514]
    float* act     = sm + OFF_ACT;    // 2 x [64][66]
    float* gates_s = sm + OFF_GATES;  // [64][20]
    float* bias_s  = sm + OFF_BIAS;   // [32]

    const int tid = threadIdx.x;
    const int cta = blockIdx.x;
    const int gp  = tid & 7;    // gate-pair: rows 2gp, 2gp+1
    const int bq  = tid >> 3;   // batch quad: batches bq*4..bq*4+3
    const int w   = tid >> 5;   // warp id
    const int c2  = tid & 31;   // lane

    // Load this CTA's weight rows into SMEM (once per launch).
    // wr = l*32 + mat*16 + lr;  mat 0 = w_ih, 1 = w_hh.
#pragma unroll 1
    for (int wr = 0; wr < 64; wr++) {
        int l   = wr >> 5;
        int mat = (wr >> 4) & 1;
        int lr  = wr & 15;
        int gr  = (lr & 3) * HH + cta * 4 + (lr >> 2);
        const float* src = (mat ? w_hh : w_ih) + ((size_t)l * 4 * HH + gr) * HH;
        float4 v = __ldg(reinterpret_cast<const float4*>(src) + tid);
        float* d = w_s + wr * WS_STRIDE + tid * 4;
        *reinterpret_cast<float2*>(d)     = make_float2(v.x, v.y);
        *reinterpret_cast<float2*>(d + 2) = make_float2(v.z, v.w);
    }
    if (tid < 32) {
        int l  = tid >> 4;
        int lr = tid & 15;
        int gr = (lr & 3) * HH + cta * 4 + (lr >> 2);
        bias_s[tid] = b_ih[(size_t)l * 4 * HH + gr] + b_hh[(size_t)l * 4 * HH + gr];
    }
    __syncthreads();

    // Persistent cell state: (layer fixed by unroll, rr in 0..1) ->
    // idx = tid + rr*128, b = idx&63, ul = idx>>6.
    float c0[2] = {0.f, 0.f};
    float c1[2] = {0.f, 0.f};

#pragma unroll 1
    for (int t = 0; t < TT; t++) {
        const int p = t & 1;
#pragma unroll
        for (int l = 0; l < 2; l++) {
            const float* inp = (l == 0) ? (g_inp + (size_t)t * BB * HH)
                                        : g_hbuf[0][p ^ 1];
            const float* hp = g_hbuf[l][p];
            float*       hd = g_hbuf[l][p ^ 1];

            float2 acc[4][2];
#pragma unroll
            for (int i = 0; i < 4; i++) {
                acc[i][0] = make_float2(0.f, 0.f);
                acc[i][1] = make_float2(0.f, 0.f);
            }

#pragma unroll 1
            for (int pass = 0; pass < 2; pass++) {
                const float* src = pass ? hp : inp;
                const float* w0p = w_s + ((l * 2 + pass) * 16 + 2 * gp) * WS_STRIDE;
                const float* w1p = w0p + WS_STRIDE;

                float2 r[16];
                ldg_chunk(src, 0, w, c2, r);
                sts_chunk(act, w, c2, r);
#pragma unroll 1
                for (int c = 0; c < 8; c++) {
                    if (c < 7) ldg_chunk(src, (c + 1) * 64, w, c2, r);
                    __syncthreads();
                    compute_chunk(act + (c & 1) * ACT_BUF,
                                  w0p + c * 64, w1p + c * 64, bq, acc);
                    if (c < 7) sts_chunk(act + ((c + 1) & 1) * ACT_BUF, w, c2, r);
                }
            }

            // Finalize gates into SMEM: gates_s[b][lr], lr = ul*4 + gt.
#pragma unroll
            for (int i = 0; i < 4; i++) {
#pragma unroll
                for (int j = 0; j < 2; j++) {
                    gates_s[(bq * 4 + i) * 20 + 2 * gp + j] =
                        acc[i][j].x + acc[i][j].y + bias_s[l * 16 + 2 * gp + j];
                }
            }
            __syncthreads();

            // Cell update: 2 (unit,batch) pairs per thread; c in registers.
            float* creg = (l == 0) ? c0 : c1;
#pragma unroll
            for (int rr = 0; rr < 2; rr++) {
                int idx = tid + rr * 128;
                int b   = idx & 63;
                int ul  = idx >> 6;
                float4 gv = *reinterpret_cast<const float4*>(gates_s + b * 20 + ul * 4);
                float ig = sigm(gv.x);
                float fg = sigm(gv.y);
                float gg = tanh_a(gv.z);
                float og = sigm(gv.w);
                float cn = fmaf(fg, creg[rr], ig * gg);
                float hn = og * tanh_a(cn);
                creg[rr] = cn;
                int col = cta * 4 + ul;
                __stcg(hd + b * HH + col, hn);
                if (l == 1) {
                    __stcg(g_h1all + ((size_t)t * BB + b) * HH + col, hn);
                }
            }
            gbar();
        }
    }
}

// ---------------------------------------------------------------------------
// Zero the h double-buffers (c lives in registers, h0/c0 start at zero).
// ---------------------------------------------------------------------------
__global__ void zero_hbuf_kernel() {
    int i = blockIdx.x * blockDim.x + threadIdx.x;
    (&g_hbuf[0][0][0])[i] = 0.f;   // grid sized exactly
}

// ---------------------------------------------------------------------------
// Tiled NT sgemm: C[M,N] = act( A[M,K] @ B[N,K]^T + bias[N] ), fp32, f32x2 FMA.
// BM=BN=64, BK=32, 256 threads, 4x4 micro-tile. act: 0=none, 1=sigmoid.
// Requires M%64==0, N%64==0, K%32==0 (holds for both uses).
// ---------------------------------------------------------------------------
__global__ void __launch_bounds__(256) gemm_nt_kernel(
    const float* __restrict__ A, const float* __restrict__ B,
    const float* __restrict__ bias, float* __restrict__ C,
    int M, int N, int K, int act)
{
    __shared__ float As[64 * 38];
    __shared__ float Bs[64 * 38];
    const int tid = threadIdx.x;
    const int tx = tid & 15;
    const int ty = tid >> 4;
    const int m0 = blockIdx.x * 64;
    const int n0 = blockIdx.y * 64;

    float2 acc[4][4];
#pragma unroll
    for (int i = 0; i < 4; i++)
#pragma unroll
        for (int j = 0; j < 4; j++) acc[i][j] = make_float2(0.f, 0.f);

    for (int k0 = 0; k0 < K; k0 += 32) {
        __syncthreads();
#pragma unroll
        for (int it = 0; it < 2; it++) {
            int idx = tid + it * 256;          // 0..511
            int r   = idx >> 3;                // 0..63
            int cc  = (idx & 7) * 4;           // 0..28
            float4 va = __ldg(reinterpret_cast<const float4*>(
                A + (size_t)(m0 + r) * K + k0 + cc));
            float* da = As + r * 38 + cc;
            *reinterpret_cast<float2*>(da)     = make_float2(va.x, va.y);
            *reinterpret_cast<float2*>(da + 2) = make_float2(va.z, va.w);
            float4 vb = __ldg(reinterpret_cast<const float4*>(
                B + (size_t)(n0 + r) * K + k0 + cc));
            float* db = Bs + r * 38 + cc;
            *reinterpret_cast<float2*>(db)     = make_float2(vb.x, vb.y);
            *reinterpret_cast<float2*>(db + 2) = make_float2(vb.z, vb.w);
        }
        __syncthreads();
#pragma unroll
        for (int kk = 0; kk < 32; kk += 2) {
            float2 a2[4], b2[4];
#pragma unroll
            for (int i = 0; i < 4; i++)
                a2[i] = *reinterpret_cast<const float2*>(As + (ty + 16 * i) * 38 + kk);
#pragma unroll
            for (int j = 0; j < 4; j++)
                b2[j] = *reinterpret_cast<const float2*>(Bs + (tx + 16 * j) * 38 + kk);
#pragma unroll
            for (int i = 0; i < 4; i++)
#pragma unroll
                for (int j = 0; j < 4; j++)
                    acc[i][j] = ffma2(a2[i], b2[j], acc[i][j]);
        }
    }

#pragma unroll
    for (int i = 0; i < 4; i++) {
        int m = m0 + ty + 16 * i;
#pragma unroll
        for (int j = 0; j < 4; j++) {
            int n = n0 + tx + 16 * j;
            float v = acc[i][j].x + acc[i][j].y + __ldg(bias + n);
            if (act) v = 1.0f / (1.0f + __expf(-v));
            C[(size_t)m * N + n] = v;
        }
    }
}

// ---------------------------------------------------------------------------
// Launch: pre-GEMM (input proj + sigmoid) -> persistent LSTM -> post-GEMM.
// Inputs (metadata order): x, w_in, b_in, w_ih, w_hh, b_ih, b_hh, w_out, b_out
// ---------------------------------------------------------------------------
extern "C" void kernel_launch(void* const* d_in, const int* in_sizes, int n_in,
                              void* d_out, int out_size) {
    const float* x     = (const float*)d_in[0];
    const float* w_in  = (const float*)d_in[1];
    const float* b_in  = (const float*)d_in[2];
    const float* w_ih  = (const float*)d_in[3];
    const float* w_hh  = (const float*)d_in[4];
    const float* b_ih  = (const float*)d_in[5];
    const float* b_hh  = (const float*)d_in[6];
    const float* w_out = (const float*)d_in[7];
    const float* b_out = (const float*)d_in[8];
    float* out = (float*)d_out;

    cudaFuncSetAttribute(lstm_kernel,
                         cudaFuncAttributeMaxDynamicSharedMemorySize, SMEM_BYTES);

    void* p_inp = nullptr;
    void* p_h1  = nullptr;
    cudaGetSymbolAddress(&p_inp, g_inp);
    cudaGetSymbolAddress(&p_h1, g_h1all);

    // Zero h state (131072 elements exactly).
    zero_hbuf_kernel<<<512, 256>>>();

    // inp_all = sigmoid(x @ w_in^T + b_in):  [65536,512], K=128
    gemm_nt_kernel<<<dim3(TT * BB / 64, HH / 64), 256>>>(
        x, w_in, b_in, (float*)p_inp, TT * BB, HH, II, 1);

    // Recurrence (writes g_h1all)
    lstm_kernel<<<NCTA, NTHR, SMEM_BYTES>>>(w_ih, w_hh, b_ih, b_hh);

    // out = h1_all @ w_out^T + b_out:  [65536,128], K=512
    gemm_nt_kernel<<<dim3(TT * BB / 64, II / 64), 256>>>(
        (const float*)p_h1, w_out, b_out, out, TT * BB, II, HH, 0);
}